// round 2
// baseline (speedup 1.0000x reference)
#include <cuda_runtime.h>
#include <math.h>

// Problem constants
#define SEQ   16384
#define DHID  1280
#define NH    16
#define HD    80
#define WSZ   64
#define NW    (SEQ / WSZ)      // 256
#define QKVN  (3 * DHID)       // 3840

// Scratch (device globals — no allocation allowed in kernel_launch)
__device__ float g_qkv[(size_t)SEQ * QKVN];    // 252 MB: [S, 3*D] = [S][t][h][d]
__device__ float g_attn[(size_t)SEQ * DHID];   // 84 MB:  [S, H*HD]

// ---------------------------------------------------------------------------
// SGEMM (NT): C[m,n] = sum_k A[m,k] * B[n,k] + bias[n]
// A: [M,K] row-major, B: [N,K] row-major. M,N multiples of 128, K multiple of 8.
// 128x128 block tile, BK=8, 256 threads, 8x8 per-thread microtile.
// ---------------------------------------------------------------------------
__global__ void __launch_bounds__(256) sgemm_nt_bias(
    const float* __restrict__ A, const float* __restrict__ B,
    const float* __restrict__ bias, float* __restrict__ C,
    int M, int N, int K)
{
    __shared__ float As[8][128];
    __shared__ float Bs[8][128];

    const int tid = threadIdx.x;
    const int bm = blockIdx.y * 128;
    const int bn = blockIdx.x * 128;
    const int tx = tid & 15;        // 0..15 -> n microtile
    const int ty = tid >> 4;        // 0..15 -> m microtile

    const int lr = tid >> 1;        // load row within tile (0..127)
    const int lc = (tid & 1) * 4;   // load col within BK (0 or 4)

    const float* Ap = A + (size_t)(bm + lr) * K + lc;
    const float* Bp = B + (size_t)(bn + lr) * K + lc;

    float acc[8][8];
    #pragma unroll
    for (int i = 0; i < 8; i++)
        #pragma unroll
        for (int j = 0; j < 8; j++) acc[i][j] = 0.0f;

    for (int k0 = 0; k0 < K; k0 += 8) {
        float4 av = *(const float4*)(Ap + k0);
        float4 bv = *(const float4*)(Bp + k0);
        As[lc + 0][lr] = av.x; As[lc + 1][lr] = av.y;
        As[lc + 2][lr] = av.z; As[lc + 3][lr] = av.w;
        Bs[lc + 0][lr] = bv.x; Bs[lc + 1][lr] = bv.y;
        Bs[lc + 2][lr] = bv.z; Bs[lc + 3][lr] = bv.w;
        __syncthreads();

        #pragma unroll
        for (int kk = 0; kk < 8; kk++) {
            float a[8], b[8];
            *(float4*)&a[0] = *(const float4*)&As[kk][ty * 8];
            *(float4*)&a[4] = *(const float4*)&As[kk][ty * 8 + 4];
            *(float4*)&b[0] = *(const float4*)&Bs[kk][tx * 8];
            *(float4*)&b[4] = *(const float4*)&Bs[kk][tx * 8 + 4];
            #pragma unroll
            for (int i = 0; i < 8; i++)
                #pragma unroll
                for (int j = 0; j < 8; j++)
                    acc[i][j] = fmaf(a[i], b[j], acc[i][j]);
        }
        __syncthreads();
    }

    // epilogue: + bias, vectorized stores
    float bsv[8];
    *(float4*)&bsv[0] = *(const float4*)&bias[bn + tx * 8];
    *(float4*)&bsv[4] = *(const float4*)&bias[bn + tx * 8 + 4];
    #pragma unroll
    for (int i = 0; i < 8; i++) {
        const int row = bm + ty * 8 + i;
        float4 o0, o1;
        o0.x = acc[i][0] + bsv[0]; o0.y = acc[i][1] + bsv[1];
        o0.z = acc[i][2] + bsv[2]; o0.w = acc[i][3] + bsv[3];
        o1.x = acc[i][4] + bsv[4]; o1.y = acc[i][5] + bsv[5];
        o1.z = acc[i][6] + bsv[6]; o1.w = acc[i][7] + bsv[7];
        float* cp = C + (size_t)row * N + bn + tx * 8;
        *(float4*)(cp + 0) = o0;
        *(float4*)(cp + 4) = o1;
    }
}

// ---------------------------------------------------------------------------
// Per-(window, head) attention with fused RoPE.
// blockIdx.x = head (16), blockIdx.y = window (256). 256 threads.
// Smem: q,k,v tiles [64][81] (padded, odd stride => conflict-free) + scores [64][64].
// ---------------------------------------------------------------------------
#define PD 81

__global__ void __launch_bounds__(256) attn_kernel(
    const float* __restrict__ qkv, const float* __restrict__ cosv,
    const float* __restrict__ sinv, const float* __restrict__ mask,
    float* __restrict__ out)
{
    const int h = blockIdx.x;
    const int w = blockIdx.y;
    extern __shared__ float sm[];
    float* qs = sm;                 // 64*81
    float* ks = qs + WSZ * PD;
    float* vs = ks + WSZ * PD;
    float* sc = vs + WSZ * PD;      // 64*64

    const int tid = threadIdx.x;

    // Load raw q,k,v tiles (rows of 80 floats, 320B contiguous each)
    #pragma unroll
    for (int r = 0; r < 20; r++) {              // 64*80/256 = 20
        int idx = tid + 256 * r;
        int s = idx / HD, d = idx - s * HD;
        const float* base = qkv + (size_t)(w * WSZ + s) * QKVN + h * HD + d;
        qs[s * PD + d] = base[0];
        ks[s * PD + d] = base[DHID];
        vs[s * PD + d] = base[2 * DHID];
    }
    __syncthreads();

    // RoPE on q,k (read all raws, then write back)
    float nq[20], nk[20];
    #pragma unroll
    for (int r = 0; r < 20; r++) {
        int idx = tid + 256 * r;
        int s = idx / HD, d = idx - s * HD;
        int gs = w * WSZ + s;
        float c  = cosv[(size_t)gs * HD + d];
        float sn = sinv[(size_t)gs * HD + d];
        int   pd  = (d < 40) ? d + 40 : d - 40;
        float sgn = (d < 40) ? -1.0f : 1.0f;
        nq[r] = qs[s * PD + d] * c + sgn * qs[s * PD + pd] * sn;
        nk[r] = ks[s * PD + d] * c + sgn * ks[s * PD + pd] * sn;
    }
    __syncthreads();
    #pragma unroll
    for (int r = 0; r < 20; r++) {
        int idx = tid + 256 * r;
        int s = idx / HD, d = idx - s * HD;
        qs[s * PD + d] = nq[r];
        ks[s * PD + d] = nk[r];
    }
    __syncthreads();

    // Scores: sc[i][j] = scale * <q_i, k_j> + mask[w][i][j]
    const float scale = 0.11180339887498949f;   // 1/sqrt(80)
    const float* mk = mask + (size_t)w * (WSZ * WSZ);
    #pragma unroll
    for (int r = 0; r < 16; r++) {              // 4096/256
        int idx = tid + 256 * r;
        int i = idx >> 6, j = idx & 63;
        const float* qrow = qs + i * PD;
        const float* krow = ks + j * PD;
        float acc = 0.0f;
        #pragma unroll
        for (int d = 0; d < HD; d++)
            acc = fmaf(qrow[d], krow[d], acc);
        sc[idx] = acc * scale + mk[idx];
    }
    __syncthreads();

    // Softmax: warp wid handles rows 8*wid..8*wid+7
    const int wid = tid >> 5, lane = tid & 31;
    #pragma unroll
    for (int rr = 0; rr < 8; rr++) {
        int i = wid * 8 + rr;
        float v0 = sc[i * 64 + lane];
        float v1 = sc[i * 64 + lane + 32];
        float m = fmaxf(v0, v1);
        #pragma unroll
        for (int off = 16; off; off >>= 1)
            m = fmaxf(m, __shfl_xor_sync(0xFFFFFFFFu, m, off));
        float e0 = expf(v0 - m), e1 = expf(v1 - m);
        float ssum = e0 + e1;
        #pragma unroll
        for (int off = 16; off; off >>= 1)
            ssum += __shfl_xor_sync(0xFFFFFFFFu, ssum, off);
        float inv = 1.0f / ssum;
        sc[i * 64 + lane]      = e0 * inv;
        sc[i * 64 + lane + 32] = e1 * inv;
    }
    __syncthreads();

    // O = P @ V, write straight into final [S, H*HD] layout
    #pragma unroll
    for (int r = 0; r < 20; r++) {
        int idx = tid + 256 * r;
        int i = idx / HD, d = idx - i * HD;
        const float* prow = sc + i * 64;
        float acc = 0.0f;
        #pragma unroll
        for (int j = 0; j < WSZ; j++)
            acc = fmaf(prow[j], vs[j * PD + d], acc);
        out[(size_t)(w * WSZ + i) * DHID + h * HD + d] = acc;
    }
}

// ---------------------------------------------------------------------------
// kernel_launch: QKV GEMM -> attention(+RoPE) -> proj GEMM
// ---------------------------------------------------------------------------
extern "C" void kernel_launch(void* const* d_in, const int* in_sizes, int n_in,
                              void* d_out, int out_size)
{
    (void)in_sizes; (void)n_in; (void)out_size;
    const float* hs     = (const float*)d_in[0];
    const float* mask   = (const float*)d_in[1];
    const float* cosv   = (const float*)d_in[2];
    const float* sinv   = (const float*)d_in[3];
    const float* qkv_w  = (const float*)d_in[4];
    const float* qkv_b  = (const float*)d_in[5];
    const float* proj_w = (const float*)d_in[6];
    const float* proj_b = (const float*)d_in[7];
    float* out = (float*)d_out;

    float *qkv, *att;
    cudaGetSymbolAddress((void**)&qkv, g_qkv);
    cudaGetSymbolAddress((void**)&att, g_attn);

    // 1) QKV GEMM + bias: [16384,1280] x [3840,1280]^T -> [16384,3840]
    sgemm_nt_bias<<<dim3(QKVN / 128, SEQ / 128), 256>>>(
        hs, qkv_w, qkv_b, qkv, SEQ, QKVN, DHID);

    // 2) Windowed attention with fused RoPE
    size_t smem = (size_t)(3 * WSZ * PD + WSZ * WSZ) * sizeof(float);  // 78592 B
    cudaFuncSetAttribute(attn_kernel, cudaFuncAttributeMaxDynamicSharedMemorySize,
                         (int)smem);
    attn_kernel<<<dim3(NH, NW), 256, smem>>>(qkv, cosv, sinv, mask, att);

    // 3) Output projection: [16384,1280] x [1280,1280]^T + bias -> d_out
    sgemm_nt_bias<<<dim3(DHID / 128, SEQ / 128), 256>>>(
        att, proj_w, proj_b, out, SEQ, DHID, DHID);
}

// round 3
// speedup vs baseline: 1.9320x; 1.9320x over previous
#include <cuda_runtime.h>
#include <math.h>
#include <stdint.h>

// Problem constants
#define SEQ   16384
#define DHID  1280
#define NH    16
#define HD    80
#define WSZ   64
#define NW    (SEQ / WSZ)      // 256
#define QKVN  (3 * DHID)       // 3840

// Scratch (device globals — no allocation allowed in kernel_launch)
__device__ float g_qkv[(size_t)SEQ * QKVN];    // 252 MB
__device__ float g_attn[(size_t)SEQ * DHID];   // 84 MB

// ---------------------------------------------------------------------------
// TF32 tensor-core GEMM (NT): C[m,n] = sum_k A[m,k]*B[n,k] + bias[n]
// A:[M,K] row-major, B:[N,K] row-major. M,N mult of 128, K mult of 16.
// 128x128 block tile, BK=16, 256 threads (8 warps: 4 in m, 2 in n).
// Warp tile 32x64 = 2x8 m16n8k8 mma tiles. Register prefetch double-buffer.
// ---------------------------------------------------------------------------
#define ASTR 20   // smem row stride in words; conflict-free for frag pattern

__device__ __forceinline__ uint32_t f2tf32(float x) {
    uint32_t y;
    asm("cvt.rna.tf32.f32 %0, %1;" : "=r"(y) : "f"(x));
    return y;
}

__device__ __forceinline__ void mma_tf32(float c[4], const uint32_t a[4],
                                         const uint32_t b[2]) {
    asm volatile(
        "mma.sync.aligned.m16n8k8.row.col.f32.tf32.tf32.f32 "
        "{%0,%1,%2,%3}, {%4,%5,%6,%7}, {%8,%9}, {%0,%1,%2,%3};"
        : "+f"(c[0]), "+f"(c[1]), "+f"(c[2]), "+f"(c[3])
        : "r"(a[0]), "r"(a[1]), "r"(a[2]), "r"(a[3]), "r"(b[0]), "r"(b[1]));
}

__global__ void __launch_bounds__(256) tf32_gemm_nt_bias(
    const float* __restrict__ A, const float* __restrict__ B,
    const float* __restrict__ bias, float* __restrict__ C,
    int M, int N, int K)
{
    __shared__ uint32_t As[128 * ASTR];
    __shared__ uint32_t Bs[128 * ASTR];

    const int tid  = threadIdx.x;
    const int lane = tid & 31;
    const int wid  = tid >> 5;
    const int warp_m = wid & 3;       // 0..3 -> 32-row slab
    const int warp_n = wid >> 2;      // 0..1 -> 64-col slab
    const int bm = blockIdx.y * 128;
    const int bn = blockIdx.x * 128;

    // Global-load mapping: each thread loads 8 consecutive floats of a
    // 128x16 tile (row = tid>>1, cols (tid&1)*8 .. +7).
    const int lrow = tid >> 1;
    const int lcol = (tid & 1) * 8;
    const float* Ap = A + (size_t)(bm + lrow) * K + lcol;
    const float* Bp = B + (size_t)(bn + lrow) * K + lcol;

    float acc[2][8][4];
    #pragma unroll
    for (int mi = 0; mi < 2; mi++)
        #pragma unroll
        for (int ni = 0; ni < 8; ni++)
            #pragma unroll
            for (int r = 0; r < 4; r++) acc[mi][ni][r] = 0.0f;

    // Prefetch iteration 0
    float4 pa0 = *(const float4*)(Ap + 0);
    float4 pa1 = *(const float4*)(Ap + 4);
    float4 pb0 = *(const float4*)(Bp + 0);
    float4 pb1 = *(const float4*)(Bp + 4);

    const int niter = K / 16;
    for (int it = 0; it < niter; ++it) {
        // Store prefetched tile to smem (tf32-converted), 16B-aligned vec stores
        {
            uint32_t* ad = &As[lrow * ASTR + lcol];
            uint32_t* bd = &Bs[lrow * ASTR + lcol];
            uint4 va0 = { f2tf32(pa0.x), f2tf32(pa0.y), f2tf32(pa0.z), f2tf32(pa0.w) };
            uint4 va1 = { f2tf32(pa1.x), f2tf32(pa1.y), f2tf32(pa1.z), f2tf32(pa1.w) };
            uint4 vb0 = { f2tf32(pb0.x), f2tf32(pb0.y), f2tf32(pb0.z), f2tf32(pb0.w) };
            uint4 vb1 = { f2tf32(pb1.x), f2tf32(pb1.y), f2tf32(pb1.z), f2tf32(pb1.w) };
            *(uint4*)(ad + 0) = va0;
            *(uint4*)(ad + 4) = va1;
            *(uint4*)(bd + 0) = vb0;
            *(uint4*)(bd + 4) = vb1;
        }
        __syncthreads();

        // Prefetch next tile while computing this one
        if (it + 1 < niter) {
            const float* Ap2 = Ap + (size_t)(it + 1) * 16;
            const float* Bp2 = Bp + (size_t)(it + 1) * 16;
            pa0 = *(const float4*)(Ap2 + 0);
            pa1 = *(const float4*)(Ap2 + 4);
            pb0 = *(const float4*)(Bp2 + 0);
            pb1 = *(const float4*)(Bp2 + 4);
        }

        // Compute: 2 k8-steps of 16 mmas each
        #pragma unroll
        for (int k8 = 0; k8 < 2; ++k8) {
            const int kb = k8 * 8 + (lane & 3);
            uint32_t afrag[2][4];
            uint32_t bfrag[8][2];
            #pragma unroll
            for (int mi = 0; mi < 2; mi++) {
                const int r = warp_m * 32 + mi * 16 + (lane >> 2);
                afrag[mi][0] = As[r * ASTR + kb];
                afrag[mi][1] = As[(r + 8) * ASTR + kb];
                afrag[mi][2] = As[r * ASTR + kb + 4];
                afrag[mi][3] = As[(r + 8) * ASTR + kb + 4];
            }
            #pragma unroll
            for (int ni = 0; ni < 8; ni++) {
                const int c = warp_n * 64 + ni * 8 + (lane >> 2);
                bfrag[ni][0] = Bs[c * ASTR + kb];
                bfrag[ni][1] = Bs[c * ASTR + kb + 4];
            }
            #pragma unroll
            for (int mi = 0; mi < 2; mi++)
                #pragma unroll
                for (int ni = 0; ni < 8; ni++)
                    mma_tf32(acc[mi][ni], afrag[mi], bfrag[ni]);
        }
        __syncthreads();
    }

    // Epilogue: + bias, float2 stores (c0,c1) and (c2,c3) pairs
    #pragma unroll
    for (int mi = 0; mi < 2; mi++) {
        const int row0 = bm + warp_m * 32 + mi * 16 + (lane >> 2);
        #pragma unroll
        for (int ni = 0; ni < 8; ni++) {
            const int col = bn + warp_n * 64 + ni * 8 + (lane & 3) * 2;
            const float b0 = bias[col], b1 = bias[col + 1];
            float2 o0 = { acc[mi][ni][0] + b0, acc[mi][ni][1] + b1 };
            float2 o1 = { acc[mi][ni][2] + b0, acc[mi][ni][3] + b1 };
            *(float2*)(C + (size_t)row0 * N + col)       = o0;
            *(float2*)(C + (size_t)(row0 + 8) * N + col) = o1;
        }
    }
}

// ---------------------------------------------------------------------------
// Per-(window, head) attention with fused RoPE (unchanged from baseline).
// ---------------------------------------------------------------------------
#define PD 81

__global__ void __launch_bounds__(256) attn_kernel(
    const float* __restrict__ qkv, const float* __restrict__ cosv,
    const float* __restrict__ sinv, const float* __restrict__ mask,
    float* __restrict__ out)
{
    const int h = blockIdx.x;
    const int w = blockIdx.y;
    extern __shared__ float sm[];
    float* qs = sm;                 // 64*81
    float* ks = qs + WSZ * PD;
    float* vs = ks + WSZ * PD;
    float* sc = vs + WSZ * PD;      // 64*64

    const int tid = threadIdx.x;

    #pragma unroll
    for (int r = 0; r < 20; r++) {              // 64*80/256 = 20
        int idx = tid + 256 * r;
        int s = idx / HD, d = idx - s * HD;
        const float* base = qkv + (size_t)(w * WSZ + s) * QKVN + h * HD + d;
        qs[s * PD + d] = base[0];
        ks[s * PD + d] = base[DHID];
        vs[s * PD + d] = base[2 * DHID];
    }
    __syncthreads();

    float nq[20], nk[20];
    #pragma unroll
    for (int r = 0; r < 20; r++) {
        int idx = tid + 256 * r;
        int s = idx / HD, d = idx - s * HD;
        int gs = w * WSZ + s;
        float c  = cosv[(size_t)gs * HD + d];
        float sn = sinv[(size_t)gs * HD + d];
        int   pd  = (d < 40) ? d + 40 : d - 40;
        float sgn = (d < 40) ? -1.0f : 1.0f;
        nq[r] = qs[s * PD + d] * c + sgn * qs[s * PD + pd] * sn;
        nk[r] = ks[s * PD + d] * c + sgn * ks[s * PD + pd] * sn;
    }
    __syncthreads();
    #pragma unroll
    for (int r = 0; r < 20; r++) {
        int idx = tid + 256 * r;
        int s = idx / HD, d = idx - s * HD;
        qs[s * PD + d] = nq[r];
        ks[s * PD + d] = nk[r];
    }
    __syncthreads();

    const float scale = 0.11180339887498949f;   // 1/sqrt(80)
    const float* mk = mask + (size_t)w * (WSZ * WSZ);
    #pragma unroll
    for (int r = 0; r < 16; r++) {              // 4096/256
        int idx = tid + 256 * r;
        int i = idx >> 6, j = idx & 63;
        const float* qrow = qs + i * PD;
        const float* krow = ks + j * PD;
        float acc = 0.0f;
        #pragma unroll
        for (int d = 0; d < HD; d++)
            acc = fmaf(qrow[d], krow[d], acc);
        sc[idx] = acc * scale + mk[idx];
    }
    __syncthreads();

    const int wid = tid >> 5, lane = tid & 31;
    #pragma unroll
    for (int rr = 0; rr < 8; rr++) {
        int i = wid * 8 + rr;
        float v0 = sc[i * 64 + lane];
        float v1 = sc[i * 64 + lane + 32];
        float m = fmaxf(v0, v1);
        #pragma unroll
        for (int off = 16; off; off >>= 1)
            m = fmaxf(m, __shfl_xor_sync(0xFFFFFFFFu, m, off));
        float e0 = expf(v0 - m), e1 = expf(v1 - m);
        float ssum = e0 + e1;
        #pragma unroll
        for (int off = 16; off; off >>= 1)
            ssum += __shfl_xor_sync(0xFFFFFFFFu, ssum, off);
        float inv = 1.0f / ssum;
        sc[i * 64 + lane]      = e0 * inv;
        sc[i * 64 + lane + 32] = e1 * inv;
    }
    __syncthreads();

    #pragma unroll
    for (int r = 0; r < 20; r++) {
        int idx = tid + 256 * r;
        int i = idx / HD, d = idx - i * HD;
        const float* prow = sc + i * 64;
        float acc = 0.0f;
        #pragma unroll
        for (int j = 0; j < WSZ; j++)
            acc = fmaf(prow[j], vs[j * PD + d], acc);
        out[(size_t)(w * WSZ + i) * DHID + h * HD + d] = acc;
    }
}

// ---------------------------------------------------------------------------
// kernel_launch: QKV GEMM (tf32) -> attention(+RoPE) -> proj GEMM (tf32)
// ---------------------------------------------------------------------------
extern "C" void kernel_launch(void* const* d_in, const int* in_sizes, int n_in,
                              void* d_out, int out_size)
{
    (void)in_sizes; (void)n_in; (void)out_size;
    const float* hs     = (const float*)d_in[0];
    const float* mask   = (const float*)d_in[1];
    const float* cosv   = (const float*)d_in[2];
    const float* sinv   = (const float*)d_in[3];
    const float* qkv_w  = (const float*)d_in[4];
    const float* qkv_b  = (const float*)d_in[5];
    const float* proj_w = (const float*)d_in[6];
    const float* proj_b = (const float*)d_in[7];
    float* out = (float*)d_out;

    float *qkv, *att;
    cudaGetSymbolAddress((void**)&qkv, g_qkv);
    cudaGetSymbolAddress((void**)&att, g_attn);

    // 1) QKV GEMM + bias: [16384,1280] x [3840,1280]^T -> [16384,3840]
    tf32_gemm_nt_bias<<<dim3(QKVN / 128, SEQ / 128), 256>>>(
        hs, qkv_w, qkv_b, qkv, SEQ, QKVN, DHID);

    // 2) Windowed attention with fused RoPE
    size_t smem = (size_t)(3 * WSZ * PD + WSZ * WSZ) * sizeof(float);  // 78592 B
    cudaFuncSetAttribute(attn_kernel, cudaFuncAttributeMaxDynamicSharedMemorySize,
                         (int)smem);
    attn_kernel<<<dim3(NH, NW), 256, smem>>>(qkv, cosv, sinv, mask, att);

    // 3) Output projection: [16384,1280] x [1280,1280]^T + bias -> d_out
    tf32_gemm_nt_bias<<<dim3(DHID / 128, SEQ / 128), 256>>>(
        att, proj_w, proj_b, out, SEQ, DHID, DHID);
}

// round 4
// speedup vs baseline: 2.3030x; 1.1921x over previous
#include <cuda_runtime.h>
#include <math.h>
#include <stdint.h>

// Problem constants
#define SEQ   16384
#define DHID  1280
#define NH    16
#define HD    80
#define WSZ   64
#define NW    (SEQ / WSZ)      // 256
#define QKVN  (3 * DHID)       // 3840

// Scratch (device globals — no allocation allowed in kernel_launch)
__device__ float g_qkv[(size_t)SEQ * QKVN];    // 252 MB
__device__ float g_attn[(size_t)SEQ * DHID];   // 84 MB

// ---------------------------------------------------------------------------
// TF32 tensor-core GEMM (NT), 2-stage cp.async pipeline.
// C[m,n] = sum_k A[m,k]*B[n,k] + bias[n]
// A:[M,K] row-major, B:[N,K] row-major. M,N mult of 128, K mult of 16.
// 128x128 block tile, BK=16, 256 threads (8 warps: 4 in m, 2 in n).
// Warp tile 32x64 = 2x8 m16n8k8 mma tiles. Raw fp32 staged in smem via
// cp.async; cvt.rna.tf32 applied at fragment-load time (numerically identical
// to converting at store time).
// ---------------------------------------------------------------------------
#define ASTR 20   // smem row stride in words; conflict-free for frag pattern

__device__ __forceinline__ uint32_t f2tf32(float x) {
    uint32_t y;
    asm("cvt.rna.tf32.f32 %0, %1;" : "=r"(y) : "f"(x));
    return y;
}
__device__ __forceinline__ uint32_t tf32_of_bits(uint32_t raw) {
    return f2tf32(__uint_as_float(raw));
}

__device__ __forceinline__ void mma_tf32(float c[4], const uint32_t a[4],
                                         const uint32_t b[2]) {
    asm volatile(
        "mma.sync.aligned.m16n8k8.row.col.f32.tf32.tf32.f32 "
        "{%0,%1,%2,%3}, {%4,%5,%6,%7}, {%8,%9}, {%0,%1,%2,%3};"
        : "+f"(c[0]), "+f"(c[1]), "+f"(c[2]), "+f"(c[3])
        : "r"(a[0]), "r"(a[1]), "r"(a[2]), "r"(a[3]), "r"(b[0]), "r"(b[1]));
}

__device__ __forceinline__ void cp_async16(uint32_t saddr, const void* gptr) {
    asm volatile("cp.async.cg.shared.global [%0], [%1], 16;\n"
                 :: "r"(saddr), "l"(gptr));
}
__device__ __forceinline__ void cp_commit() {
    asm volatile("cp.async.commit_group;\n" ::: "memory");
}
template <int N>
__device__ __forceinline__ void cp_wait() {
    asm volatile("cp.async.wait_group %0;\n" :: "n"(N) : "memory");
}

__global__ void __launch_bounds__(256) tf32_gemm_nt_bias(
    const float* __restrict__ A, const float* __restrict__ B,
    const float* __restrict__ bias, float* __restrict__ C,
    int M, int N, int K)
{
    __shared__ uint32_t As[2][128 * ASTR];   // raw fp32 bits
    __shared__ uint32_t Bs[2][128 * ASTR];

    const int tid  = threadIdx.x;
    const int lane = tid & 31;
    const int wid  = tid >> 5;
    const int warp_m = wid & 3;       // 0..3 -> 32-row slab
    const int warp_n = wid >> 2;      // 0..1 -> 64-col slab
    const int bm = blockIdx.y * 128;
    const int bn = blockIdx.x * 128;

    // Copy mapping: each thread owns row = tid>>1, cols (tid&1)*8..+7 of a
    // 128x16 stage => two 16B cp.async per matrix per stage.
    const int lrow = tid >> 1;
    const int lcol = (tid & 1) * 8;
    const float* Ap = A + (size_t)(bm + lrow) * K + lcol;
    const float* Bp = B + (size_t)(bn + lrow) * K + lcol;

    uint32_t sAaddr = (uint32_t)__cvta_generic_to_shared(
        &As[0][lrow * ASTR + lcol]);
    uint32_t sBaddr = (uint32_t)__cvta_generic_to_shared(
        &Bs[0][lrow * ASTR + lcol]);
    const uint32_t stageBytes = 128 * ASTR * 4;

    float acc[2][8][4];
    #pragma unroll
    for (int mi = 0; mi < 2; mi++)
        #pragma unroll
        for (int ni = 0; ni < 8; ni++)
            #pragma unroll
            for (int r = 0; r < 4; r++) acc[mi][ni][r] = 0.0f;

    const int niter = K / 16;

    // Preload stage 0
    cp_async16(sAaddr,      Ap);
    cp_async16(sAaddr + 16, Ap + 4);
    cp_async16(sBaddr,      Bp);
    cp_async16(sBaddr + 16, Bp + 4);
    cp_commit();

    for (int it = 0; it < niter; ++it) {
        const int cur = it & 1;
        const int nxt = cur ^ 1;

        if (it + 1 < niter) {
            const float* Ap2 = Ap + (size_t)(it + 1) * 16;
            const float* Bp2 = Bp + (size_t)(it + 1) * 16;
            const uint32_t sa = sAaddr + nxt * stageBytes;
            const uint32_t sb = sBaddr + nxt * stageBytes;
            cp_async16(sa,      Ap2);
            cp_async16(sa + 16, Ap2 + 4);
            cp_async16(sb,      Bp2);
            cp_async16(sb + 16, Bp2 + 4);
            cp_commit();
            cp_wait<1>();     // stage `cur` complete
        } else {
            cp_wait<0>();
        }
        __syncthreads();

        const uint32_t* Asc = As[cur];
        const uint32_t* Bsc = Bs[cur];
        #pragma unroll
        for (int k8 = 0; k8 < 2; ++k8) {
            const int kb = k8 * 8 + (lane & 3);
            uint32_t afrag[2][4];
            uint32_t bfrag[8][2];
            #pragma unroll
            for (int mi = 0; mi < 2; mi++) {
                const int r = warp_m * 32 + mi * 16 + (lane >> 2);
                afrag[mi][0] = tf32_of_bits(Asc[r * ASTR + kb]);
                afrag[mi][1] = tf32_of_bits(Asc[(r + 8) * ASTR + kb]);
                afrag[mi][2] = tf32_of_bits(Asc[r * ASTR + kb + 4]);
                afrag[mi][3] = tf32_of_bits(Asc[(r + 8) * ASTR + kb + 4]);
            }
            #pragma unroll
            for (int ni = 0; ni < 8; ni++) {
                const int c = warp_n * 64 + ni * 8 + (lane >> 2);
                bfrag[ni][0] = tf32_of_bits(Bsc[c * ASTR + kb]);
                bfrag[ni][1] = tf32_of_bits(Bsc[c * ASTR + kb + 4]);
            }
            #pragma unroll
            for (int mi = 0; mi < 2; mi++)
                #pragma unroll
                for (int ni = 0; ni < 8; ni++)
                    mma_tf32(acc[mi][ni], afrag[mi], bfrag[ni]);
        }
        __syncthreads();   // all reads of `cur` done before it is refilled
    }

    // Epilogue: + bias, float2 stores
    #pragma unroll
    for (int mi = 0; mi < 2; mi++) {
        const int row0 = bm + warp_m * 32 + mi * 16 + (lane >> 2);
        #pragma unroll
        for (int ni = 0; ni < 8; ni++) {
            const int col = bn + warp_n * 64 + ni * 8 + (lane & 3) * 2;
            const float b0 = bias[col], b1 = bias[col + 1];
            float2 o0 = { acc[mi][ni][0] + b0, acc[mi][ni][1] + b1 };
            float2 o1 = { acc[mi][ni][2] + b0, acc[mi][ni][3] + b1 };
            *(float2*)(C + (size_t)row0 * N + col)       = o0;
            *(float2*)(C + (size_t)(row0 + 8) * N + col) = o1;
        }
    }
}

// ---------------------------------------------------------------------------
// Per-(window, head) attention with fused RoPE (unchanged — proven correct).
// ---------------------------------------------------------------------------
#define PD 81

__global__ void __launch_bounds__(256) attn_kernel(
    const float* __restrict__ qkv, const float* __restrict__ cosv,
    const float* __restrict__ sinv, const float* __restrict__ mask,
    float* __restrict__ out)
{
    const int h = blockIdx.x;
    const int w = blockIdx.y;
    extern __shared__ float sm[];
    float* qs = sm;                 // 64*81
    float* ks = qs + WSZ * PD;
    float* vs = ks + WSZ * PD;
    float* sc = vs + WSZ * PD;      // 64*64

    const int tid = threadIdx.x;

    #pragma unroll
    for (int r = 0; r < 20; r++) {              // 64*80/256 = 20
        int idx = tid + 256 * r;
        int s = idx / HD, d = idx - s * HD;
        const float* base = qkv + (size_t)(w * WSZ + s) * QKVN + h * HD + d;
        qs[s * PD + d] = base[0];
        ks[s * PD + d] = base[DHID];
        vs[s * PD + d] = base[2 * DHID];
    }
    __syncthreads();

    float nq[20], nk[20];
    #pragma unroll
    for (int r = 0; r < 20; r++) {
        int idx = tid + 256 * r;
        int s = idx / HD, d = idx - s * HD;
        int gs = w * WSZ + s;
        float c  = cosv[(size_t)gs * HD + d];
        float sn = sinv[(size_t)gs * HD + d];
        int   pd  = (d < 40) ? d + 40 : d - 40;
        float sgn = (d < 40) ? -1.0f : 1.0f;
        nq[r] = qs[s * PD + d] * c + sgn * qs[s * PD + pd] * sn;
        nk[r] = ks[s * PD + d] * c + sgn * ks[s * PD + pd] * sn;
    }
    __syncthreads();
    #pragma unroll
    for (int r = 0; r < 20; r++) {
        int idx = tid + 256 * r;
        int s = idx / HD, d = idx - s * HD;
        qs[s * PD + d] = nq[r];
        ks[s * PD + d] = nk[r];
    }
    __syncthreads();

    const float scale = 0.11180339887498949f;   // 1/sqrt(80)
    const float* mk = mask + (size_t)w * (WSZ * WSZ);
    #pragma unroll
    for (int r = 0; r < 16; r++) {              // 4096/256
        int idx = tid + 256 * r;
        int i = idx >> 6, j = idx & 63;
        const float* qrow = qs + i * PD;
        const float* krow = ks + j * PD;
        float acc = 0.0f;
        #pragma unroll
        for (int d = 0; d < HD; d++)
            acc = fmaf(qrow[d], krow[d], acc);
        sc[idx] = acc * scale + mk[idx];
    }
    __syncthreads();

    const int wid = tid >> 5, lane = tid & 31;
    #pragma unroll
    for (int rr = 0; rr < 8; rr++) {
        int i = wid * 8 + rr;
        float v0 = sc[i * 64 + lane];
        float v1 = sc[i * 64 + lane + 32];
        float m = fmaxf(v0, v1);
        #pragma unroll
        for (int off = 16; off; off >>= 1)
            m = fmaxf(m, __shfl_xor_sync(0xFFFFFFFFu, m, off));
        float e0 = expf(v0 - m), e1 = expf(v1 - m);
        float ssum = e0 + e1;
        #pragma unroll
        for (int off = 16; off; off >>= 1)
            ssum += __shfl_xor_sync(0xFFFFFFFFu, ssum, off);
        float inv = 1.0f / ssum;
        sc[i * 64 + lane]      = e0 * inv;
        sc[i * 64 + lane + 32] = e1 * inv;
    }
    __syncthreads();

    #pragma unroll
    for (int r = 0; r < 20; r++) {
        int idx = tid + 256 * r;
        int i = idx / HD, d = idx - i * HD;
        const float* prow = sc + i * 64;
        float acc = 0.0f;
        #pragma unroll
        for (int j = 0; j < WSZ; j++)
            acc = fmaf(prow[j], vs[j * PD + d], acc);
        out[(size_t)(w * WSZ + i) * DHID + h * HD + d] = acc;
    }
}

// ---------------------------------------------------------------------------
// kernel_launch: QKV GEMM (tf32) -> attention(+RoPE) -> proj GEMM (tf32)
// ---------------------------------------------------------------------------
extern "C" void kernel_launch(void* const* d_in, const int* in_sizes, int n_in,
                              void* d_out, int out_size)
{
    (void)in_sizes; (void)n_in; (void)out_size;
    const float* hs     = (const float*)d_in[0];
    const float* mask   = (const float*)d_in[1];
    const float* cosv   = (const float*)d_in[2];
    const float* sinv   = (const float*)d_in[3];
    const float* qkv_w  = (const float*)d_in[4];
    const float* qkv_b  = (const float*)d_in[5];
    const float* proj_w = (const float*)d_in[6];
    const float* proj_b = (const float*)d_in[7];
    float* out = (float*)d_out;

    float *qkv, *att;
    cudaGetSymbolAddress((void**)&qkv, g_qkv);
    cudaGetSymbolAddress((void**)&att, g_attn);

    // 1) QKV GEMM + bias: [16384,1280] x [3840,1280]^T -> [16384,3840]
    tf32_gemm_nt_bias<<<dim3(QKVN / 128, SEQ / 128), 256>>>(
        hs, qkv_w, qkv_b, qkv, SEQ, QKVN, DHID);

    // 2) Windowed attention with fused RoPE
    size_t smem = (size_t)(3 * WSZ * PD + WSZ * WSZ) * sizeof(float);  // 78592 B
    cudaFuncSetAttribute(attn_kernel, cudaFuncAttributeMaxDynamicSharedMemorySize,
                         (int)smem);
    attn_kernel<<<dim3(NH, NW), 256, smem>>>(qkv, cosv, sinv, mask, att);

    // 3) Output projection: [16384,1280] x [1280,1280]^T + bias -> d_out
    tf32_gemm_nt_bias<<<dim3(DHID / 128, SEQ / 128), 256>>>(
        att, proj_w, proj_b, out, SEQ, DHID, DHID);
}